// round 4
// baseline (speedup 1.0000x reference)
#include <cuda_runtime.h>

#define B_  16
#define S_  128
#define T_  128
#define ST_ 127
#define E_  256
#define H_  512
#define H2_ 1024
#define H3_ 1536
#define KD_ 1280
#define KO_ 1792
#define V_  32000

// ---------------- scratch (device globals; no allocation allowed) ----------------
__device__ float g_emb    [B_*S_*E_];
__device__ float g_emb_rev[B_*S_*E_];
__device__ float g_emb_in [ST_*B_*E_];
__device__ float g_GI_f   [B_*S_*H3_];
__device__ float g_GI_b   [B_*S_*H3_];
__device__ float g_GIe    [ST_*B_*H3_];
__device__ float g_enc_out[B_*S_*H2_];
__device__ float g_out_bR [B_*S_*H_];
__device__ float g_encP   [B_*S_*H_];
__device__ float g_feat   [ST_*B_*KO_];   // [t*16+b][ h(512) | ctx(1024) | e(256) ]
__device__ float g_hf  [2*B_*H_];
__device__ float g_hb  [2*B_*H_];
__device__ float g_hdec[2*B_*H_];

// ---------------- helpers ----------------
__device__ __forceinline__ float sigf(float x) { return 1.f / (1.f + expf(-x)); }

__device__ __forceinline__ unsigned long long f2pack(float a, float b) {
    unsigned long long r;
    asm("mov.b64 %0, {%1, %2};" : "=l"(r) : "r"(__float_as_uint(a)), "r"(__float_as_uint(b)));
    return r;
}
__device__ __forceinline__ void f2fma(unsigned long long& d, unsigned long long a, unsigned long long b) {
    asm("fma.rn.f32x2 %0, %1, %2, %0;" : "+l"(d) : "l"(a), "l"(b));
}
__device__ __forceinline__ float2 f2unpack(unsigned long long v) {
    unsigned lo, hi;
    asm("mov.b64 {%0, %1}, %2;" : "=r"(lo), "=r"(hi) : "l"(v));
    return make_float2(__uint_as_float(lo), __uint_as_float(hi));
}

// ---------------- gathers + init ----------------
__global__ void k_gather(const int* __restrict__ src, const int* __restrict__ len,
                         const int* __restrict__ tgt,
                         const float* __restrict__ enc_emb, const float* __restrict__ dec_emb)
{
    const int total = B_*S_*E_;
    for (int i = blockIdx.x*blockDim.x + threadIdx.x; i < total; i += gridDim.x*blockDim.x) {
        int e = i % E_;
        int s = (i / E_) % S_;
        int b = i / (E_*S_);
        int L = len[b];
        g_emb[i] = enc_emb[(size_t)src[b*S_+s]*E_ + e];
        int r = (s < L) ? (L-1-s) : s;
        g_emb_rev[i] = enc_emb[(size_t)src[b*S_+r]*E_ + e];
        if (s < ST_) {
            float v = dec_emb[(size_t)tgt[b*T_+s]*E_ + e];
            size_t n = (size_t)s*B_ + b;
            g_emb_in[n*E_ + e] = v;
            g_feat[n*KO_ + (H_+H2_) + e] = v;    // e_t section of logit features
        }
        if (i < 2*B_*H_) { g_hf[i] = 0.f; g_hb[i] = 0.f; }
    }
}

// ---------------- generic tiled GEMM: C[m][n] = sum_k A[m][k]*W[n][k] (+bias[n]) ----------------
// A: [M,K] (lda=K). W: [N, ldw] row-major, uses first K cols. N must be multiple of 128.
// remap!=0: C row m -> d_out row (b*127 + t) with b=m%16, t=m/16 (logits transpose).
__global__ __launch_bounds__(256, 2)
void k_gemm(const float* __restrict__ A, const float* __restrict__ W,
            const float* __restrict__ bias, float* __restrict__ C,
            int M, int N, int K, int ldw, int remap)
{
    __shared__ float As[16][132];
    __shared__ float Bs[16][132];
    const int tid = threadIdx.x;
    const int tx = tid & 15, ty = tid >> 4;
    const int m0 = blockIdx.y * 128;
    const int n0 = blockIdx.x * 128;
    const int lr = tid >> 2;          // 0..63
    const int lc = (tid & 3) * 4;     // 0,4,8,12

    unsigned long long acc[8][4];
    #pragma unroll
    for (int i = 0; i < 8; i++)
        #pragma unroll
        for (int j = 0; j < 4; j++) acc[i][j] = 0ULL;

    for (int k0 = 0; k0 < K; k0 += 16) {
        #pragma unroll
        for (int h = 0; h < 2; h++) {
            int m = m0 + lr + h*64;
            float4 v = (m < M) ? *(const float4*)(A + (size_t)m*K + k0 + lc)
                               : make_float4(0.f,0.f,0.f,0.f);
            As[lc+0][lr+h*64] = v.x; As[lc+1][lr+h*64] = v.y;
            As[lc+2][lr+h*64] = v.z; As[lc+3][lr+h*64] = v.w;
        }
        #pragma unroll
        for (int h = 0; h < 2; h++) {
            int n = n0 + lr + h*64;
            float4 v = *(const float4*)(W + (size_t)n*ldw + k0 + lc);
            Bs[lc+0][lr+h*64] = v.x; Bs[lc+1][lr+h*64] = v.y;
            Bs[lc+2][lr+h*64] = v.z; Bs[lc+3][lr+h*64] = v.w;
        }
        __syncthreads();
        #pragma unroll
        for (int k = 0; k < 16; k++) {
            float4 a0 = *(const float4*)&As[k][ty*8];
            float4 a1 = *(const float4*)&As[k][ty*8+4];
            float4 b0 = *(const float4*)&Bs[k][tx*8];
            float4 b1 = *(const float4*)&Bs[k][tx*8+4];
            float ra[8] = {a0.x,a0.y,a0.z,a0.w,a1.x,a1.y,a1.z,a1.w};
            unsigned long long bp[4];
            bp[0] = f2pack(b0.x, b0.y); bp[1] = f2pack(b0.z, b0.w);
            bp[2] = f2pack(b1.x, b1.y); bp[3] = f2pack(b1.z, b1.w);
            #pragma unroll
            for (int i = 0; i < 8; i++) {
                unsigned long long ap = f2pack(ra[i], ra[i]);
                f2fma(acc[i][0], ap, bp[0]);
                f2fma(acc[i][1], ap, bp[1]);
                f2fma(acc[i][2], ap, bp[2]);
                f2fma(acc[i][3], ap, bp[3]);
            }
        }
        __syncthreads();
    }

    #pragma unroll
    for (int i = 0; i < 8; i++) {
        int m = m0 + ty*8 + i;
        if (m >= M) continue;
        float* crow = remap ? (C + ((size_t)(m & 15) * ST_ + (m >> 4)) * N)
                            : (C + (size_t)m * N);
        int nc = n0 + tx*8;
        #pragma unroll
        for (int j = 0; j < 4; j++) {
            float2 v = f2unpack(acc[i][j]);
            float c0 = v.x, c1 = v.y;
            if (bias) { c0 += bias[nc+2*j]; c1 += bias[nc+2*j+1]; }
            crow[nc+2*j]   = c0;
            crow[nc+2*j+1] = c1;
        }
    }
}

// ---------------- encoder GRU step (both directions): h-side GEMV + gates ----------------
__global__ void k_enc_step(const float* __restrict__ W_hh_f, const float* __restrict__ b_hh_f,
                           const float* __restrict__ W_hh_b, const float* __restrict__ b_hh_b,
                           const int* __restrict__ len, int t)
{
    const int dir = blockIdx.y;
    const int tid = threadIdx.x;
    const int b = tid & 15;
    const int j = blockIdx.x * 16 + (tid >> 4);

    const float* Whh = dir ? W_hh_b : W_hh_f;
    const float* bhh = dir ? b_hh_b : b_hh_f;
    float* hbase = dir ? g_hb : g_hf;
    const float* hrow  = hbase + (t & 1)     * (B_*H_) + b*H_;
    float*       hnrow = hbase + ((t+1) & 1) * (B_*H_) + b*H_;
    const float* GI = (dir ? g_GI_b : g_GI_f) + ((size_t)(b*S_ + t)) * H3_;

    const float* Wr = Whh + (size_t)j * H_;
    const float* Wz = Wr + (size_t)H_*H_;
    const float* Wn = Wz + (size_t)H_*H_;

    float ar = 0.f, az = 0.f, an = 0.f;
    #pragma unroll 4
    for (int k = 0; k < H_; k += 4) {
        float4 hv = *(const float4*)(hrow + k);
        float4 wr = *(const float4*)(Wr + k);
        float4 wz = *(const float4*)(Wz + k);
        float4 wn = *(const float4*)(Wn + k);
        ar = fmaf(hv.x,wr.x, fmaf(hv.y,wr.y, fmaf(hv.z,wr.z, fmaf(hv.w,wr.w, ar))));
        az = fmaf(hv.x,wz.x, fmaf(hv.y,wz.y, fmaf(hv.z,wz.z, fmaf(hv.w,wz.w, az))));
        an = fmaf(hv.x,wn.x, fmaf(hv.y,wn.y, fmaf(hv.z,wn.z, fmaf(hv.w,wn.w, an))));
    }
    float hr = ar + bhh[j], hz = az + bhh[H_+j], hn = an + bhh[2*H_+j];
    float r = sigf(GI[j]      + hr);
    float z = sigf(GI[H_+j]   + hz);
    float n = tanhf(GI[2*H_+j] + r*hn);
    float hold = hrow[j];
    float hnew = (1.f - z)*n + z*hold;
    bool valid = t < len[b];
    hnrow[j] = valid ? hnew : hold;
    float o = valid ? hnew : 0.f;
    if (dir == 0) g_enc_out[((size_t)(b*S_+t))*H2_ + j] = o;
    else          g_out_bR [((size_t)(b*S_+t))*H_  + j] = o;
}

// ---------------- scatter backward outputs into enc_out (un-reverse) ----------------
__global__ void k_outbw(const int* __restrict__ len)
{
    int i = blockIdx.x*blockDim.x + threadIdx.x;
    if (i >= B_*S_*H_) return;
    int j = i % H_;
    int s = (i / H_) % S_;
    int b = i / (H_*S_);
    int L = len[b];
    int r = (s < L) ? (L-1-s) : s;
    g_enc_out[((size_t)(b*S_+s))*H2_ + H_ + j] = g_out_bR[((size_t)(b*S_+r))*H_ + j];
}

// ---------------- bridge: h0_dec = tanh([h_f,h_b] @ bridge_W.T + b) ----------------
__global__ void k_bridge(const float* __restrict__ bridge_W, const float* __restrict__ bridge_b)
{
    const int tid = threadIdx.x;
    const int b = tid & 15;
    const int j = blockIdx.x * 16 + (tid >> 4);
    const float* Wrow = bridge_W + (size_t)j * H2_;
    const float* hf = g_hf + b*H_;   // final state lands in parity buffer 0
    const float* hb = g_hb + b*H_;
    float acc = 0.f;
    #pragma unroll 4
    for (int k = 0; k < H_; k += 4) {
        float4 h = *(const float4*)(hf + k);
        float4 w = *(const float4*)(Wrow + k);
        acc = fmaf(h.x,w.x, fmaf(h.y,w.y, fmaf(h.z,w.z, fmaf(h.w,w.w, acc))));
    }
    #pragma unroll 4
    for (int k = 0; k < H_; k += 4) {
        float4 h = *(const float4*)(hb + k);
        float4 w = *(const float4*)(Wrow + H_ + k);
        acc = fmaf(h.x,w.x, fmaf(h.y,w.y, fmaf(h.z,w.z, fmaf(h.w,w.w, acc))));
    }
    g_hdec[b*H_ + j] = tanhf(acc + bridge_b[j]);
}

// ---------------- fused attention per decode step: dp, energy, softmax, ctx ----------------
__global__ void k_attn(const float* __restrict__ Wa_dec, const float* __restrict__ Wv,
                       const int* __restrict__ src, int t)
{
    __shared__ float hsm[H_];
    __shared__ float dps[H_];
    __shared__ float wvs[H_];
    __shared__ float esm[S_];
    __shared__ float sinv;
    const int b = blockIdx.x;
    const int tid = threadIdx.x;
    const int lane = tid & 31, w = tid >> 5;

    const float* hrow = g_hdec + (t & 1)*(B_*H_) + b*H_;
    for (int k = tid; k < H_; k += 256) { hsm[k] = hrow[k]; wvs[k] = Wv[k]; }
    __syncthreads();

    // dp[j] = h . Wa_dec[j]
    for (int jj = w*64; jj < w*64 + 64; jj++) {
        const float* wa = Wa_dec + (size_t)jj * H_;
        float s = 0.f;
        #pragma unroll
        for (int i = 0; i < 16; i++) { int k = lane + 32*i; s = fmaf(wa[k], hsm[k], s); }
        #pragma unroll
        for (int o = 16; o; o >>= 1) s += __shfl_xor_sync(0xffffffffu, s, o);
        if (lane == 0) dps[jj] = s;
    }
    __syncthreads();

    // energy[s] = sum_j tanh(encP[b,s,j] + dp[j]) * Wv[j], masked
    const float* ePb = g_encP + (size_t)b*S_*H_;
    for (int s0 = w; s0 < S_; s0 += 8) {
        const float* er = ePb + (size_t)s0 * H_;
        float acc = 0.f;
        #pragma unroll
        for (int i = 0; i < 16; i++) {
            int k = lane + 32*i;
            acc = fmaf(tanhf(er[k] + dps[k]), wvs[k], acc);
        }
        #pragma unroll
        for (int o = 16; o; o >>= 1) acc += __shfl_xor_sync(0xffffffffu, acc, o);
        if (lane == 0) esm[s0] = (src[b*S_ + s0] != 0) ? acc : -1e9f;
    }
    __syncthreads();

    if (w == 0) {
        float v[4]; float m = -1e30f;
        #pragma unroll
        for (int i = 0; i < 4; i++) { v[i] = esm[lane + 32*i]; m = fmaxf(m, v[i]); }
        #pragma unroll
        for (int o = 16; o; o >>= 1) m = fmaxf(m, __shfl_xor_sync(0xffffffffu, m, o));
        float sum = 0.f;
        #pragma unroll
        for (int i = 0; i < 4; i++) { v[i] = expf(v[i] - m); sum += v[i]; }
        #pragma unroll
        for (int o = 16; o; o >>= 1) sum += __shfl_xor_sync(0xffffffffu, sum, o);
        #pragma unroll
        for (int i = 0; i < 4; i++) esm[lane + 32*i] = v[i];
        if (lane == 0) sinv = 1.f / sum;
    }
    __syncthreads();

    // ctx[j] = sum_s attn[s] * enc_out[b,s,j]; write into feat ctx section
    const float* eo = g_enc_out + (size_t)b*S_*H2_;
    const int j4 = tid * 4;
    float c0=0.f,c1=0.f,c2=0.f,c3=0.f;
    for (int s0 = 0; s0 < S_; s0++) {
        float a = esm[s0];
        float4 v = *(const float4*)(eo + (size_t)s0*H2_ + j4);
        c0 = fmaf(a, v.x, c0); c1 = fmaf(a, v.y, c1);
        c2 = fmaf(a, v.z, c2); c3 = fmaf(a, v.w, c3);
    }
    float inv = sinv;
    *(float4*)(g_feat + ((size_t)(t*B_ + b))*KO_ + H_ + j4) =
        make_float4(c0*inv, c1*inv, c2*inv, c3*inv);
}

// ---------------- decoder GRU step: gi(ctx part) + gh + gates ----------------
__global__ void k_dec(const float* __restrict__ W_ih_d, const float* __restrict__ W_hh_d,
                      const float* __restrict__ b_hh_d, int t)
{
    const int tid = threadIdx.x;
    const int b = tid & 15;
    const int j = blockIdx.x * 16 + (tid >> 4);
    const size_t n = (size_t)t*B_ + b;

    const float* gi = g_GIe + n * H3_;
    float air = gi[j], aiz = gi[H_+j], ain = gi[2*H_+j];

    const float* xr = g_feat + n*KO_ + H_;                 // ctx (1024)
    const float* Wr = W_ih_d + (size_t)j        * KD_ + E_;
    const float* Wz = W_ih_d + (size_t)(H_+j)   * KD_ + E_;
    const float* Wn = W_ih_d + (size_t)(2*H_+j) * KD_ + E_;
    #pragma unroll 4
    for (int k = 0; k < H2_; k += 4) {
        float4 x  = *(const float4*)(xr + k);
        float4 wr = *(const float4*)(Wr + k);
        float4 wz = *(const float4*)(Wz + k);
        float4 wn = *(const float4*)(Wn + k);
        air = fmaf(x.x,wr.x, fmaf(x.y,wr.y, fmaf(x.z,wr.z, fmaf(x.w,wr.w, air))));
        aiz = fmaf(x.x,wz.x, fmaf(x.y,wz.y, fmaf(x.z,wz.z, fmaf(x.w,wz.w, aiz))));
        ain = fmaf(x.x,wn.x, fmaf(x.y,wn.y, fmaf(x.z,wn.z, fmaf(x.w,wn.w, ain))));
    }

    const float* hrow = g_hdec + (t & 1)*(B_*H_) + b*H_;
    const float* Vr = W_hh_d + (size_t)j * H_;
    const float* Vz = Vr + (size_t)H_*H_;
    const float* Vn = Vz + (size_t)H_*H_;
    float ahr = 0.f, ahz = 0.f, ahn = 0.f;
    #pragma unroll 4
    for (int k = 0; k < H_; k += 4) {
        float4 h  = *(const float4*)(hrow + k);
        float4 wr = *(const float4*)(Vr + k);
        float4 wz = *(const float4*)(Vz + k);
        float4 wn = *(const float4*)(Vn + k);
        ahr = fmaf(h.x,wr.x, fmaf(h.y,wr.y, fmaf(h.z,wr.z, fmaf(h.w,wr.w, ahr))));
        ahz = fmaf(h.x,wz.x, fmaf(h.y,wz.y, fmaf(h.z,wz.z, fmaf(h.w,wz.w, ahz))));
        ahn = fmaf(h.x,wn.x, fmaf(h.y,wn.y, fmaf(h.z,wn.z, fmaf(h.w,wn.w, ahn))));
    }
    ahr += b_hh_d[j]; ahz += b_hh_d[H_+j]; ahn += b_hh_d[2*H_+j];

    float r = sigf(air + ahr);
    float z = sigf(aiz + ahz);
    float nn = tanhf(ain + r*ahn);
    float hold = hrow[j];
    float hnew = (1.f - z)*nn + z*hold;

    g_hdec[((t+1) & 1)*(B_*H_) + b*H_ + j] = hnew;
    g_feat[n*KO_ + j] = hnew;
}

// ---------------- launch ----------------
extern "C" void kernel_launch(void* const* d_in, const int* in_sizes, int n_in,
                              void* d_out, int out_size)
{
    const int*   src      = (const int*)d_in[0];
    const int*   len      = (const int*)d_in[1];
    const int*   tgt      = (const int*)d_in[2];
    const float* enc_emb  = (const float*)d_in[3];
    const float* W_ih_f   = (const float*)d_in[4];
    const float* W_hh_f   = (const float*)d_in[5];
    const float* b_ih_f   = (const float*)d_in[6];
    const float* b_hh_f   = (const float*)d_in[7];
    const float* W_ih_b   = (const float*)d_in[8];
    const float* W_hh_b   = (const float*)d_in[9];
    const float* b_ih_b   = (const float*)d_in[10];
    const float* b_hh_b   = (const float*)d_in[11];
    const float* bridge_W = (const float*)d_in[12];
    const float* bridge_b = (const float*)d_in[13];
    const float* dec_emb  = (const float*)d_in[14];
    const float* Wa_enc   = (const float*)d_in[15];
    const float* Wa_dec   = (const float*)d_in[16];
    const float* Wv       = (const float*)d_in[17];
    const float* W_ih_d   = (const float*)d_in[18];
    const float* W_hh_d   = (const float*)d_in[19];
    const float* b_ih_d   = (const float*)d_in[20];
    const float* b_hh_d   = (const float*)d_in[21];
    const float* out_W    = (const float*)d_in[22];
    const float* out_b    = (const float*)d_in[23];
    float* out = (float*)d_out;

    float* p_emb     = nullptr; cudaGetSymbolAddress((void**)&p_emb,     g_emb);
    float* p_emb_rev = nullptr; cudaGetSymbolAddress((void**)&p_emb_rev, g_emb_rev);
    float* p_emb_in  = nullptr; cudaGetSymbolAddress((void**)&p_emb_in,  g_emb_in);
    float* p_GI_f    = nullptr; cudaGetSymbolAddress((void**)&p_GI_f,    g_GI_f);
    float* p_GI_b    = nullptr; cudaGetSymbolAddress((void**)&p_GI_b,    g_GI_b);
    float* p_GIe     = nullptr; cudaGetSymbolAddress((void**)&p_GIe,     g_GIe);
    float* p_enc_out = nullptr; cudaGetSymbolAddress((void**)&p_enc_out, g_enc_out);
    float* p_encP    = nullptr; cudaGetSymbolAddress((void**)&p_encP,    g_encP);
    float* p_feat    = nullptr; cudaGetSymbolAddress((void**)&p_feat,    g_feat);

    // 1. gathers (emb, emb_rev, dec emb -> feat e-section) + zero h0
    k_gather<<<512, 256>>>(src, len, tgt, enc_emb, dec_emb);

    // 2. input-side gate GEMMs (parallel over all timesteps)
    k_gemm<<<dim3(H3_/128, (B_*S_)/128), 256>>>(p_emb,     W_ih_f, b_ih_f, p_GI_f, B_*S_,  H3_, E_, E_,  0);
    k_gemm<<<dim3(H3_/128, (B_*S_)/128), 256>>>(p_emb_rev, W_ih_b, b_ih_b, p_GI_b, B_*S_,  H3_, E_, E_,  0);
    k_gemm<<<dim3(H3_/128, (ST_*B_+127)/128), 256>>>(p_emb_in, W_ih_d, b_ih_d, p_GIe, ST_*B_, H3_, E_, KD_, 0);

    // 3. encoder recurrence (fwd+bwd concurrently per step)
    for (int t = 0; t < S_; t++)
        k_enc_step<<<dim3(H_/16, 2), 256>>>(W_hh_f, b_hh_f, W_hh_b, b_hh_b, len, t);

    // 4. un-reverse backward outputs, bridge, encoder projection
    k_outbw<<<(B_*S_*H_)/256, 256>>>(len);
    k_bridge<<<H_/16, 256>>>(bridge_W, bridge_b);
    k_gemm<<<dim3(H_/128, (B_*S_)/128), 256>>>(p_enc_out, Wa_enc, nullptr, p_encP, B_*S_, H_, H2_, H2_, 0);

    // 5. decoder recurrence
    for (int t = 0; t < ST_; t++) {
        k_attn<<<B_, 256>>>(Wa_dec, Wv, src, t);
        k_dec<<<H_/16, 256>>>(W_ih_d, W_hh_d, b_hh_d, t);
    }

    // 6. output projection (dominant GEMM), rows remapped to [B, 127, V]
    k_gemm<<<dim3(V_/128, (ST_*B_+127)/128), 256>>>(p_feat, out_W, out_b, out, ST_*B_, V_, KO_, KO_, 1);
}

// round 6
// speedup vs baseline: 1.5397x; 1.5397x over previous
#include <cuda_runtime.h>
#include <cuda_bf16.h>

#define B_  16
#define S_  128
#define T_  128
#define ST_ 127
#define E_  256
#define H_  512
#define H2_ 1024
#define H3_ 1536
#define KD_ 1280
#define KO_ 1792
#define V_  32000
#define MPAD_ 2048
#define K3_ (3*KO_)

typedef unsigned int u32;
typedef unsigned long long u64;

__device__ float g_emb    [B_*S_*E_];
__device__ float g_emb_rev[B_*S_*E_];
__device__ float g_emb_in [ST_*B_*E_];
__device__ float g_GI_f   [B_*S_*H3_];
__device__ float g_GI_b   [B_*S_*H3_];
__device__ float g_GIe    [ST_*B_*H3_];
__device__ float g_enc_out[B_*S_*H2_];
__device__ float g_out_bR [B_*S_*H_];
__device__ float g_encP   [B_*S_*H_];
__device__ float g_encW   [B_*S_*H3_];
__device__ float g_feat   [ST_*B_*KO_];
__device__ float g_hf  [2*B_*H_];
__device__ float g_hb  [2*B_*H_];
__device__ float g_hdec[2*B_*H_];
__device__ __nv_bfloat16 g_A3[(size_t)MPAD_*K3_];
__device__ __nv_bfloat16 g_B3[(size_t)V_*K3_];

__device__ __forceinline__ float sigf(float x) { return 1.f / (1.f + expf(-x)); }
__device__ __forceinline__ float tanhap(float x) {
    float y; asm("tanh.approx.f32 %0, %1;" : "=f"(y) : "f"(x)); return y;
}
__device__ __forceinline__ u64 f2pack(float a, float b) {
    u64 r; asm("mov.b64 %0, {%1, %2};" : "=l"(r) : "r"(__float_as_uint(a)), "r"(__float_as_uint(b)));
    return r;
}
__device__ __forceinline__ void f2fma(u64& d, u64 a, u64 b) {
    asm("fma.rn.f32x2 %0, %1, %2, %0;" : "+l"(d) : "l"(a), "l"(b));
}
__device__ __forceinline__ float2 f2unpack(u64 v) {
    unsigned lo, hi; asm("mov.b64 {%0, %1}, %2;" : "=r"(lo), "=r"(hi) : "l"(v));
    return make_float2(__uint_as_float(lo), __uint_as_float(hi));
}
__device__ __forceinline__ void dot3_512(const float* __restrict__ x,
    const float* __restrict__ r0, const float* __restrict__ r1,
    const float* __restrict__ r2, float& o0, float& o1, float& o2)
{
    u64 a0=0,a1=0,b0=0,b1=0,c0=0,c1=0;
    #pragma unroll 8
    for (int k = 0; k < H_; k += 4) {
        float4 xv = *(const float4*)(x + k);
        u64 xlo = f2pack(xv.x, xv.y), xhi = f2pack(xv.z, xv.w);
        float4 w0 = *(const float4*)(r0 + k);
        f2fma(a0, xlo, f2pack(w0.x, w0.y)); f2fma(a1, xhi, f2pack(w0.z, w0.w));
        float4 w1 = *(const float4*)(r1 + k);
        f2fma(b0, xlo, f2pack(w1.x, w1.y)); f2fma(b1, xhi, f2pack(w1.z, w1.w));
        float4 w2 = *(const float4*)(r2 + k);
        f2fma(c0, xlo, f2pack(w2.x, w2.y)); f2fma(c1, xhi, f2pack(w2.z, w2.w));
    }
    float2 p, q;
    p = f2unpack(a0); q = f2unpack(a1); o0 = (p.x + q.x) + (p.y + q.y);
    p = f2unpack(b0); q = f2unpack(b1); o1 = (p.x + q.x) + (p.y + q.y);
    p = f2unpack(c0); q = f2unpack(c1); o2 = (p.x + q.x) + (p.y + q.y);
}

__device__ __forceinline__ u32 s2u(const void* p) {
    u32 a; asm("{ .reg .u64 t; cvta.to.shared.u64 t, %1; cvt.u32.u64 %0, t; }" : "=r"(a) : "l"(p));
    return a;
}
__device__ __forceinline__ void cpa16(u32 dst, const void* src) {
    asm volatile("cp.async.cg.shared.global [%0], [%1], 16;" :: "r"(dst), "l"(src));
}
__device__ __forceinline__ void ldmA4(u32 addr, u32* a) {
    asm volatile("ldmatrix.sync.aligned.m8n8.x4.shared.b16 {%0,%1,%2,%3}, [%4];"
        : "=r"(a[0]), "=r"(a[1]), "=r"(a[2]), "=r"(a[3]) : "r"(addr));
}
__device__ __forceinline__ void ldmB2(u32 addr, u32* b) {
    asm volatile("ldmatrix.sync.aligned.m8n8.x2.shared.b16 {%0,%1}, [%2];"
        : "=r"(b[0]), "=r"(b[1]) : "r"(addr));
}
__device__ __forceinline__ void mma16816(float* c, const u32* a, const u32* b) {
    asm volatile("mma.sync.aligned.m16n8k16.row.col.f32.bf16.bf16.f32 "
        "{%0,%1,%2,%3}, {%4,%5,%6,%7}, {%8,%9}, {%0,%1,%2,%3};"
        : "+f"(c[0]), "+f"(c[1]), "+f"(c[2]), "+f"(c[3])
        : "r"(a[0]), "r"(a[1]), "r"(a[2]), "r"(a[3]), "r"(b[0]), "r"(b[1]));
}

// ---------------- gathers + init ----------------
__global__ void k_gather(const int* __restrict__ src, const int* __restrict__ len,
                         const int* __restrict__ tgt,
                         const float* __restrict__ enc_emb, const float* __restrict__ dec_emb)
{
    const int total = B_*S_*E_;
    for (int i = blockIdx.x*blockDim.x + threadIdx.x; i < total; i += gridDim.x*blockDim.x) {
        int e = i % E_, s = (i / E_) % S_, b = i / (E_*S_);
        int L = len[b];
        g_emb[i] = enc_emb[(size_t)src[b*S_+s]*E_ + e];
        int r = (s < L) ? (L-1-s) : s;
        g_emb_rev[i] = enc_emb[(size_t)src[b*S_+r]*E_ + e];
        if (s < ST_) {
            float v = dec_emb[(size_t)tgt[b*T_+s]*E_ + e];
            size_t n = (size_t)s*B_ + b;
            g_emb_in[n*E_ + e] = v;
            g_feat[n*KO_ + (H_+H2_) + e] = v;
        }
        if (i < 2*B_*H_) { g_hf[i] = 0.f; g_hb[i] = 0.f; }
    }
}

// ---------------- bf16 hi/lo split: A3=[hi|hi|lo], B3=[hi|lo|hi] ----------------
__global__ void k_convW(const float* __restrict__ W)
{
    const size_t total = (size_t)V_*KO_;
    for (size_t i = (size_t)blockIdx.x*blockDim.x + threadIdx.x; i < total;
         i += (size_t)gridDim.x*blockDim.x) {
        size_t n = i / KO_, k = i % KO_;
        float w = W[i];
        __nv_bfloat16 h = __float2bfloat16(w);
        __nv_bfloat16 l = __float2bfloat16(w - __bfloat162float(h));
        __nv_bfloat16* row = g_B3 + n*K3_;
        row[k] = h; row[KO_+k] = l; row[2*KO_+k] = h;
    }
}
__global__ void k_convA()
{
    const size_t total = (size_t)MPAD_*KO_;
    for (size_t i = (size_t)blockIdx.x*blockDim.x + threadIdx.x; i < total;
         i += (size_t)gridDim.x*blockDim.x) {
        size_t m = i / KO_, k = i % KO_;
        float a = (m < (size_t)(ST_*B_)) ? g_feat[i] : 0.f;
        __nv_bfloat16 h = __float2bfloat16(a);
        __nv_bfloat16 l = __float2bfloat16(a - __bfloat162float(h));
        __nv_bfloat16* row = g_A3 + m*K3_;
        row[k] = h; row[KO_+k] = h; row[2*KO_+k] = l;
    }
}

// ---------------- HMMA output GEMM: out = A3 @ B3.T + bias, row remap ----------------
// CTA: 128x128 tile, 8 warps (2x4), warp tile 64x32. BK=32, double-buffered cp.async.
// smem rows padded to 80B (40 bf16) -> ldmatrix conflict-free.
#define LDS_ 40
__global__ __launch_bounds__(256, 2)
void k_outgemm(float* __restrict__ out, const float* __restrict__ bias)
{
    __shared__ __align__(16) __nv_bfloat16 sA[2][128*LDS_];
    __shared__ __align__(16) __nv_bfloat16 sB[2][128*LDS_];
    const int tid = threadIdx.x, wid = tid >> 5, lane = tid & 31;
    const int wm = wid >> 2, wn = wid & 3;
    const int m0 = blockIdx.x * 128;   // m fastest -> B tiles L2-resident
    const int n0 = blockIdx.y * 128;

    float acc[4][4][4];
    #pragma unroll
    for (int i = 0; i < 4; i++)
        #pragma unroll
        for (int j = 0; j < 4; j++)
            #pragma unroll
            for (int q = 0; q < 4; q++) acc[i][j][q] = 0.f;

    const int NC = K3_ / 32;
    const int r0 = tid >> 2, sg0 = tid & 3;   // idx = tid: r in 0..63
    // each thread: 2 A segs + 2 B segs per tile (idx tid and tid+256)
    auto issue = [&](int c, int buf) {
        int kc = c * 32;
        #pragma unroll
        for (int h = 0; h < 2; h++) {
            int r = r0 + h*64;
            cpa16(s2u(&sA[buf][r*LDS_ + sg0*8]), g_A3 + (size_t)(m0 + r)*K3_ + kc + sg0*8);
            cpa16(s2u(&sB[buf][r*LDS_ + sg0*8]), g_B3 + (size_t)(n0 + r)*K3_ + kc + sg0*8);
        }
        asm volatile("cp.async.commit_group;");
    };

    issue(0, 0);
    for (int c = 0; c < NC; c++) {
        int buf = c & 1;
        if (c + 1 < NC) {
            issue(c + 1, buf ^ 1);
            asm volatile("cp.async.wait_group 1;" ::: "memory");
        } else {
            asm volatile("cp.async.wait_group 0;" ::: "memory");
        }
        __syncthreads();
        const u32 aB = s2u(&sA[buf][0]);
        const u32 bB = s2u(&sB[buf][0]);
        #pragma unroll
        for (int ks = 0; ks < 2; ks++) {
            u32 af[4][4], bf[4][2];
            #pragma unroll
            for (int fm = 0; fm < 4; fm++)
                ldmA4(aB + (u32)((wm*64 + fm*16 + (lane & 15))*(LDS_*2) + ks*32 + (lane >> 4)*16), af[fm]);
            #pragma unroll
            for (int fn = 0; fn < 4; fn++)
                ldmB2(bB + (u32)((wn*32 + fn*8 + (lane & 7))*(LDS_*2) + ks*32 + ((lane >> 3) & 1)*16), bf[fn]);
            #pragma unroll
            for (int fm = 0; fm < 4; fm++)
                #pragma unroll
                for (int fn = 0; fn < 4; fn++)
                    mma16816(acc[fm][fn], af[fm], bf[fn]);
        }
        __syncthreads();
    }

    // epilogue: acc[fm][fn]: rows m0+wm*64+fm*16+{l>>2, +8}, cols n0+wn*32+fn*8+(l&3)*2
    #pragma unroll
    for (int fm = 0; fm < 4; fm++) {
        #pragma unroll
        for (int half = 0; half < 2; half++) {
            int m = m0 + wm*64 + fm*16 + (lane >> 2) + half*8;
            if (m >= ST_*B_) continue;
            float* orow = out + ((size_t)((m & 15)*ST_ + (m >> 4)))*V_;
            #pragma unroll
            for (int fn = 0; fn < 4; fn++) {
                int nc = n0 + wn*32 + fn*8 + (lane & 3)*2;
                float2 v;
                v.x = acc[fm][fn][half*2 + 0] + bias[nc];
                v.y = acc[fm][fn][half*2 + 1] + bias[nc + 1];
                *(float2*)(orow + nc) = v;
            }
        }
    }
}

// ---------------- SIMT f32 GEMM for the small matmuls ----------------
__global__ __launch_bounds__(256, 2)
void k_gemm(const float* __restrict__ A, const float* __restrict__ W,
            const float* __restrict__ bias, float* __restrict__ C,
            int M, int N, int K, int ldw)
{
    __shared__ float As[16][132];
    __shared__ float Bs[16][132];
    const int tid = threadIdx.x;
    const int tx = tid & 15, ty = tid >> 4;
    const int m0 = blockIdx.y * 128, n0 = blockIdx.x * 128;
    const int lr = tid >> 2, lc = (tid & 3) * 4;

    u64 acc[8][4];
    #pragma unroll
    for (int i = 0; i < 8; i++)
        #pragma unroll
        for (int j = 0; j < 4; j++) acc[i][j] = 0ULL;

    for (int k0 = 0; k0 < K; k0 += 16) {
        #pragma unroll
        for (int h = 0; h < 2; h++) {
            int m = m0 + lr + h*64;
            float4 v = (m < M) ? *(const float4*)(A + (size_t)m*K + k0 + lc)
                               : make_float4(0.f,0.f,0.f,0.f);
            As[lc+0][lr+h*64] = v.x; As[lc+1][lr+h*64] = v.y;
            As[lc+2][lr+h*64] = v.z; As[lc+3][lr+h*64] = v.w;
        }
        #pragma unroll
        for (int h = 0; h < 2; h++) {
            int n = n0 + lr + h*64;
            float4 v = *(const float4*)(W + (size_t)n*ldw + k0 + lc);
            Bs[lc+0][lr+h*64] = v.x; Bs[lc+1][lr+h*64] = v.y;
            Bs[lc+2][lr+h*64] = v.z; Bs[lc+3][lr+h*64] = v.w;
        }
        __syncthreads();
        #pragma unroll
        for (int k = 0; k < 16; k++) {
            float4 a0 = *(const float4*)&As[k][ty*8];
            float4 a1 = *(const float4*)&As[k][ty*8+4];
            float4 b0 = *(const float4*)&Bs[k][tx*8];
            float4 b1 = *(const float4*)&Bs[k][tx*8+4];
            float ra[8] = {a0.x,a0.y,a0.z,a0.w,a1.x,a1.y,a1.z,a1.w};
            u64 bp[4];
            bp[0] = f2pack(b0.x, b0.y); bp[1] = f2pack(b0.z, b0.w);
            bp[2] = f2pack(b1.x, b1.y); bp[3] = f2pack(b1.z, b1.w);
            #pragma unroll
            for (int i = 0; i < 8; i++) {
                u64 ap = f2pack(ra[i], ra[i]);
                f2fma(acc[i][0], ap, bp[0]); f2fma(acc[i][1], ap, bp[1]);
                f2fma(acc[i][2], ap, bp[2]); f2fma(acc[i][3], ap, bp[3]);
            }
        }
        __syncthreads();
    }
    #pragma unroll
    for (int i = 0; i < 8; i++) {
        int m = m0 + ty*8 + i;
        if (m >= M) continue;
        float* crow = C + (size_t)m*N;
        int nc = n0 + tx*8;
        #pragma unroll
        for (int j = 0; j < 4; j++) {
            float2 v = f2unpack(acc[i][j]);
            float c0 = v.x, c1 = v.y;
            if (bias) { c0 += bias[nc+2*j]; c1 += bias[nc+2*j+1]; }
            crow[nc+2*j] = c0; crow[nc+2*j+1] = c1;
        }
    }
}

// ---------------- encoder GRU step ----------------
__global__ void k_enc_step(const float* __restrict__ W_hh_f, const float* __restrict__ b_hh_f,
                           const float* __restrict__ W_hh_b, const float* __restrict__ b_hh_b,
                           const int* __restrict__ len, int t)
{
    const int dir = blockIdx.y, tid = threadIdx.x;
    const int b = tid & 15, j = blockIdx.x * 16 + (tid >> 4);
    const float* Whh = dir ? W_hh_b : W_hh_f;
    const float* bhh = dir ? b_hh_b : b_hh_f;
    float* hbase = dir ? g_hb : g_hf;
    const float* hrow  = hbase + (t & 1)*(B_*H_) + b*H_;
    float*       hnrow = hbase + ((t+1) & 1)*(B_*H_) + b*H_;
    const float* GI = (dir ? g_GI_b : g_GI_f) + ((size_t)(b*S_ + t))*H3_;

    float ar, az, an;
    dot3_512(hrow, Whh + (size_t)j*H_, Whh + (size_t)(H_+j)*H_, Whh + (size_t)(2*H_+j)*H_, ar, az, an);
    float r = sigf(GI[j]       + ar + bhh[j]);
    float z = sigf(GI[H_+j]    + az + bhh[H_+j]);
    float n = tanhf(GI[2*H_+j] + r*(an + bhh[2*H_+j]));
    float hold = hrow[j];
    float hnew = (1.f - z)*n + z*hold;
    bool valid = t < len[b];
    hnrow[j] = valid ? hnew : hold;
    float o = valid ? hnew : 0.f;
    if (dir == 0) g_enc_out[((size_t)(b*S_+t))*H2_ + j] = o;
    else          g_out_bR [((size_t)(b*S_+t))*H_  + j] = o;
}

__global__ void k_outbw(const int* __restrict__ len)
{
    int i = blockIdx.x*blockDim.x + threadIdx.x;
    if (i >= B_*S_*H_) return;
    int j = i % H_, s = (i / H_) % S_, b = i / (H_*S_);
    int L = len[b];
    int r = (s < L) ? (L-1-s) : s;
    g_enc_out[((size_t)(b*S_+s))*H2_ + H_ + j] = g_out_bR[((size_t)(b*S_+r))*H_ + j];
}

__global__ void k_bridge(const float* __restrict__ bridge_W, const float* __restrict__ bridge_b)
{
    const int tid = threadIdx.x;
    const int b = tid & 15, j = blockIdx.x * 16 + (tid >> 4);
    const float* Wrow = bridge_W + (size_t)j*H2_;
    const float* hf = g_hf + b*H_;
    const float* hb = g_hb + b*H_;
    float acc = 0.f;
    #pragma unroll 4
    for (int k = 0; k < H_; k += 4) {
        float4 h = *(const float4*)(hf + k);
        float4 w = *(const float4*)(Wrow + k);
        acc = fmaf(h.x,w.x, fmaf(h.y,w.y, fmaf(h.z,w.z, fmaf(h.w,w.w, acc))));
    }
    #pragma unroll 4
    for (int k = 0; k < H_; k += 4) {
        float4 h = *(const float4*)(hb + k);
        float4 w = *(const float4*)(Wrow + H_ + k);
        acc = fmaf(h.x,w.x, fmaf(h.y,w.y, fmaf(h.z,w.z, fmaf(h.w,w.w, acc))));
    }
    g_hdec[b*H_ + j] = tanhf(acc + bridge_b[j]);
}

// ---------------- fused decoder step: attn + ctx + gic + GRU ----------------
__global__ __launch_bounds__(256)
void k_step(const float* __restrict__ Wa_dec, const float* __restrict__ Wv,
            const int* __restrict__ src, const float* __restrict__ W_hh_d,
            const float* __restrict__ b_hh_d, int t)
{
    __shared__ float hsm[H_], dps[H_], wvs[H_], esm[S_], gic[H3_];
    __shared__ float sinv;
    const int b = blockIdx.x, tid = threadIdx.x;
    const int lane = tid & 31, w = tid >> 5;

    const float* hrow = g_hdec + (t & 1)*(B_*H_) + b*H_;
    for (int k = tid; k < H_; k += 256) { hsm[k] = hrow[k]; wvs[k] = Wv[k]; }
    __syncthreads();

    for (int jj = w*64; jj < w*64 + 64; jj++) {
        const float* wa = Wa_dec + (size_t)jj*H_;
        float s = 0.f;
        #pragma unroll
        for (int i = 0; i < 16; i++) { int k = lane + 32*i; s = fmaf(wa[k], hsm[k], s); }
        #pragma unroll
        for (int o = 16; o; o >>= 1) s += __shfl_xor_sync(0xffffffffu, s, o);
        if (lane == 0) dps[jj] = s;
    }
    __syncthreads();

    const float* ePb = g_encP + (size_t)b*S_*H_;
    for (int s0 = w; s0 < S_; s0 += 8) {
        const float* er = ePb + (size_t)s0*H_;
        float acc = 0.f;
        #pragma unroll
        for (int i = 0; i < 16; i++) {
            int k = lane + 32*i;
            acc = fmaf(tanhap(er[k] + dps[k]), wvs[k], acc);
        }
        #pragma unroll
        for (int o = 16; o; o >>= 1) acc += __shfl_xor_sync(0xffffffffu, acc, o);
        if (lane == 0) esm[s0] = (src[b*S_ + s0] != 0) ? acc : -1e9f;
    }
    __syncthreads();

    if (w == 0) {
        float v[4]; float m = -1e30f;
        #pragma unroll
        for (int i = 0; i < 4; i++) { v[i] = esm[lane + 32*i]; m = fmaxf(m, v[i]); }
        #pragma unroll
        for (int o = 16; o; o >>= 1) m = fmaxf(m, __shfl_xor_sync(0xffffffffu, m, o));
        float sum = 0.f;
        #pragma unroll
        for (int i = 0; i < 4; i++) { v[i] = expf(v[i] - m); sum += v[i]; }
        #pragma unroll
        for (int o = 16; o; o >>= 1) sum += __shfl_xor_sync(0xffffffffu, sum, o);
        #pragma unroll
        for (int i = 0; i < 4; i++) esm[lane + 32*i] = v[i];
        if (lane == 0) sinv = 1.f / sum;
    }
    __syncthreads();

    float ac[4] = {0,0,0,0};
    float ag[6] = {0,0,0,0,0,0};
    const float* eo = g_enc_out + (size_t)b*S_*H2_;
    const float* ew = g_encW   + (size_t)b*S_*H3_;
    for (int s0 = 0; s0 < S_; s0++) {
        float a = esm[s0];
        const float* e1 = eo + (size_t)s0*H2_;
        const float* e2 = ew + (size_t)s0*H3_;
        #pragma unroll
        for (int i = 0; i < 4; i++) ac[i] = fmaf(a, e1[tid + i*256], ac[i]);
        #pragma unroll
        for (int i = 0; i < 6; i++) ag[i] = fmaf(a, e2[tid + i*256], ag[i]);
    }
    float inv = sinv;
    size_t n = (size_t)t*B_ + b;
    #pragma unroll
    for (int i = 0; i < 4; i++) g_feat[n*KO_ + H_ + tid + i*256] = ac[i]*inv;
    #pragma unroll
    for (int i = 0; i < 6; i++) gic[tid + i*256] = ag[i]*inv;
    __syncthreads();

    const float* gie = g_GIe + n*H3_;
    float* hn = g_hdec + ((t+1) & 1)*(B_*H_) + b*H_;
    #pragma unroll
    for (int jj = 0; jj < 2; jj++) {
        int j = tid + jj*256;
        float ar, az, an;
        dot3_512(hsm, W_hh_d + (size_t)j*H_, W_hh_d + (size_t)(H_+j)*H_,
                 W_hh_d + (size_t)(2*H_+j)*H_, ar, az, an);
        float r  = sigf(gie[j]       + gic[j]       + ar + b_hh_d[j]);
        float z  = sigf(gie[H_+j]    + gic[H_+j]    + az + b_hh_d[H_+j]);
        float nn = tanhf(gie[2*H_+j] + gic[2*H_+j]  + r*(an + b_hh_d[2*H_+j]));
        float hold = hsm[j];
        float hnew = (1.f - z)*nn + z*hold;
        hn[j] = hnew;
        g_feat[n*KO_ + j] = hnew;
    }
}

extern "C" void kernel_launch(void* const* d_in, const int* in_sizes, int n_in,
                              void* d_out, int out_size)
{
    const int*   src      = (const int*)d_in[0];
    const int*   len      = (const int*)d_in[1];
    const int*   tgt      = (const int*)d_in[2];
    const float* enc_emb  = (const float*)d_in[3];
    const float* W_ih_f   = (const float*)d_in[4];
    const float* W_hh_f   = (const float*)d_in[5];
    const float* b_ih_f   = (const float*)d_in[6];
    const float* b_hh_f   = (const float*)d_in[7];
    const float* W_ih_b   = (const float*)d_in[8];
    const float* W_hh_b   = (const float*)d_in[9];
    const float* b_ih_b   = (const float*)d_in[10];
    const float* b_hh_b   = (const float*)d_in[11];
    const float* bridge_W = (const float*)d_in[12];
    const float* bridge_b = (const float*)d_in[13];
    const float* dec_emb  = (const float*)d_in[14];
    const float* Wa_enc   = (const float*)d_in[15];
    const float* Wa_dec   = (const float*)d_in[16];
    const float* Wv       = (const float*)d_in[17];
    const float* W_ih_d   = (const float*)d_in[18];
    const float* W_hh_d   = (const float*)d_in[19];
    const float* b_ih_d   = (const float*)d_in[20];
    const float* b_hh_d   = (const float*)d_in[21];
    const float* out_W    = (const float*)d_in[22];
    const float* out_b    = (const float*)d_in[23];
    float* out = (float*)d_out;

    float *p_emb, *p_emb_rev, *p_emb_in, *p_GI_f, *p_GI_b, *p_GIe, *p_enc_out, *p_encP, *p_encW;
    cudaGetSymbolAddress((void**)&p_emb,     g_emb);
    cudaGetSymbolAddress((void**)&p_emb_rev, g_emb_rev);
    cudaGetSymbolAddress((void**)&p_emb_in,  g_emb_in);
    cudaGetSymbolAddress((void**)&p_GI_f,    g_GI_f);
    cudaGetSymbolAddress((void**)&p_GI_b,    g_GI_b);
    cudaGetSymbolAddress((void**)&p_GIe,     g_GIe);
    cudaGetSymbolAddress((void**)&p_enc_out, g_enc_out);
    cudaGetSymbolAddress((void**)&p_encP,    g_encP);
    cudaGetSymbolAddress((void**)&p_encW,    g_encW);

    // weight conversion (independent; overlaps with encoder chain on GPU)
    k_convW<<<1024, 256>>>(out_W);
    k_gather<<<512, 256>>>(src, len, tgt, enc_emb, dec_emb);

    k_gemm<<<dim3(H3_/128, (B_*S_)/128), 256>>>(p_emb,     W_ih_f, b_ih_f, p_GI_f, B_*S_,  H3_, E_, E_);
    k_gemm<<<dim3(H3_/128, (B_*S_)/128), 256>>>(p_emb_rev, W_ih_b, b_ih_b, p_GI_b, B_*S_,  H3_, E_, E_);
    k_gemm<<<dim3(H3_/128, (ST_*B_+127)/128), 256>>>(p_emb_in, W_ih_d, b_ih_d, p_GIe, ST_*B_, H3_, E_, KD_);

    for (int t = 0; t < S_; t++)
        k_enc_step<<<dim3(H_/16, 2), 256>>>(W_hh_f, b_hh_f, W_hh_b, b_hh_b, len, t);

    k_outbw<<<(B_*S_*H_)/256, 256>>>(len);
    k_bridge<<<H_/16, 256>>>(bridge_W, bridge_b);
    k_gemm<<<dim3(H_/128, (B_*S_)/128), 256>>>(p_enc_out, Wa_enc, 0, p_encP, B_*S_, H_, H2_, H2_);
    k_gemm<<<dim3(H3_/128, (B_*S_)/128), 256>>>(p_enc_out, W_ih_d + E_, 0, p_encW, B_*S_, H3_, H2_, KD_);

    for (int t = 0; t < ST_; t++)
        k_step<<<B_, 256>>>(Wa_dec, Wv, src, W_hh_d, b_hh_d, t);

    k_convA<<<1024, 256>>>();
    k_outgemm<<<dim3(MPAD_/128, V_/128), 256>>>(out, out_b);
}

// round 7
// speedup vs baseline: 3.2955x; 2.1403x over previous
#include <cuda_runtime.h>
#include <cuda_bf16.h>

#define B_  16
#define S_  128
#define T_  128
#define ST_ 127
#define E_  256
#define H_  512
#define H2_ 1024
#define H3_ 1536
#define KD_ 1280
#define KO_ 1792
#define V_  32000
#define MPAD_ 2048
#define K3_ (3*KO_)
#define HP_ 516   // padded h row stride (floats); 516*4 % 16 == 0

typedef unsigned int u32;
typedef unsigned long long u64;

__device__ float g_emb    [B_*S_*E_];
__device__ float g_emb_rev[B_*S_*E_];
__device__ float g_emb_in [ST_*B_*E_];
__device__ float g_GI_f   [B_*S_*H3_];
__device__ float g_GI_b   [B_*S_*H3_];
__device__ float g_GIe    [ST_*B_*H3_];
__device__ float g_enc_out[B_*S_*H2_];
__device__ float g_out_bR [B_*S_*H_];
__device__ float g_encP   [B_*S_*H_];
__device__ float g_encW   [B_*S_*H3_];
__device__ float g_feat   [ST_*B_*KO_];
__device__ float g_hf  [2*B_*H_];
__device__ float g_hb  [2*B_*H_];
__device__ float g_hdec[2*B_*H_];
__device__ float g_dps [B_*H_];
__device__ float g_esm [B_*S_];
__device__ float g_gict[B_*H3_];
__device__ __nv_bfloat16 g_A3[(size_t)MPAD_*K3_];
__device__ __nv_bfloat16 g_B3[(size_t)V_*K3_];

// software grid barrier state
__device__ unsigned g_cnt = 0;
__device__ unsigned g_gen = 0;

__device__ __forceinline__ void gbar(unsigned nb) {
    __syncthreads();
    if (threadIdx.x == 0) {
        unsigned old = *((volatile unsigned*)&g_gen);
        __threadfence();
        if (atomicAdd(&g_cnt, 1u) == nb - 1u) {
            g_cnt = 0u;
            __threadfence();
            atomicAdd(&g_gen, 1u);
        } else {
            while (*((volatile unsigned*)&g_gen) == old) __nanosleep(64);
            __threadfence();
        }
    }
    __syncthreads();
}

__device__ __forceinline__ float sigf(float x) { return 1.f / (1.f + expf(-x)); }
__device__ __forceinline__ float tanhap(float x) {
    float y; asm("tanh.approx.f32 %0, %1;" : "=f"(y) : "f"(x)); return y;
}
__device__ __forceinline__ u64 f2pack(float a, float b) {
    u64 r; asm("mov.b64 %0, {%1, %2};" : "=l"(r) : "r"(__float_as_uint(a)), "r"(__float_as_uint(b)));
    return r;
}
__device__ __forceinline__ void f2fma(u64& d, u64 a, u64 b) {
    asm("fma.rn.f32x2 %0, %1, %2, %0;" : "+l"(d) : "l"(a), "l"(b));
}
__device__ __forceinline__ float2 f2unpack(u64 v) {
    unsigned lo, hi; asm("mov.b64 {%0, %1}, %2;" : "=r"(lo), "=r"(hi) : "l"(v));
    return make_float2(__uint_as_float(lo), __uint_as_float(hi));
}
__device__ __forceinline__ void dot3_512(const float* __restrict__ x,
    const float* __restrict__ r0, const float* __restrict__ r1,
    const float* __restrict__ r2, float& o0, float& o1, float& o2)
{
    u64 a0=0,a1=0,b0=0,b1=0,c0=0,c1=0;
    #pragma unroll 8
    for (int k = 0; k < H_; k += 4) {
        float4 xv = *(const float4*)(x + k);
        u64 xlo = f2pack(xv.x, xv.y), xhi = f2pack(xv.z, xv.w);
        float4 w0 = *(const float4*)(r0 + k);
        f2fma(a0, xlo, f2pack(w0.x, w0.y)); f2fma(a1, xhi, f2pack(w0.z, w0.w));
        float4 w1 = *(const float4*)(r1 + k);
        f2fma(b0, xlo, f2pack(w1.x, w1.y)); f2fma(b1, xhi, f2pack(w1.z, w1.w));
        float4 w2 = *(const float4*)(r2 + k);
        f2fma(c0, xlo, f2pack(w2.x, w2.y)); f2fma(c1, xhi, f2pack(w2.z, w2.w));
    }
    float2 p, q;
    p = f2unpack(a0); q = f2unpack(a1); o0 = (p.x + q.x) + (p.y + q.y);
    p = f2unpack(b0); q = f2unpack(b1); o1 = (p.x + q.x) + (p.y + q.y);
    p = f2unpack(c0); q = f2unpack(c1); o2 = (p.x + q.x) + (p.y + q.y);
}

__device__ __forceinline__ u32 s2u(const void* p) {
    u32 a; asm("{ .reg .u64 t; cvta.to.shared.u64 t, %1; cvt.u32.u64 %0, t; }" : "=r"(a) : "l"(p));
    return a;
}
__device__ __forceinline__ void cpa16(u32 dst, const void* src) {
    asm volatile("cp.async.cg.shared.global [%0], [%1], 16;" :: "r"(dst), "l"(src));
}
__device__ __forceinline__ void ldmA4(u32 addr, u32* a) {
    asm volatile("ldmatrix.sync.aligned.m8n8.x4.shared.b16 {%0,%1,%2,%3}, [%4];"
        : "=r"(a[0]), "=r"(a[1]), "=r"(a[2]), "=r"(a[3]) : "r"(addr));
}
__device__ __forceinline__ void ldmB2(u32 addr, u32* b) {
    asm volatile("ldmatrix.sync.aligned.m8n8.x2.shared.b16 {%0,%1}, [%2];"
        : "=r"(b[0]), "=r"(b[1]) : "r"(addr));
}
__device__ __forceinline__ void mma16816(float* c, const u32* a, const u32* b) {
    asm volatile("mma.sync.aligned.m16n8k16.row.col.f32.bf16.bf16.f32 "
        "{%0,%1,%2,%3}, {%4,%5,%6,%7}, {%8,%9}, {%0,%1,%2,%3};"
        : "+f"(c[0]), "+f"(c[1]), "+f"(c[2]), "+f"(c[3])
        : "r"(a[0]), "r"(a[1]), "r"(a[2]), "r"(a[3]), "r"(b[0]), "r"(b[1]));
}

// ---------------- gathers + init ----------------
__global__ void k_gather(const int* __restrict__ src, const int* __restrict__ len,
                         const int* __restrict__ tgt,
                         const float* __restrict__ enc_emb, const float* __restrict__ dec_emb)
{
    const int total = B_*S_*E_;
    for (int i = blockIdx.x*blockDim.x + threadIdx.x; i < total; i += gridDim.x*blockDim.x) {
        int e = i % E_, s = (i / E_) % S_, b = i / (E_*S_);
        int L = len[b];
        g_emb[i] = enc_emb[(size_t)src[b*S_+s]*E_ + e];
        int r = (s < L) ? (L-1-s) : s;
        g_emb_rev[i] = enc_emb[(size_t)src[b*S_+r]*E_ + e];
        if (s < ST_) {
            float v = dec_emb[(size_t)tgt[b*T_+s]*E_ + e];
            size_t n = (size_t)s*B_ + b;
            g_emb_in[n*E_ + e] = v;
            g_feat[n*KO_ + (H_+H2_) + e] = v;
        }
        if (i < 2*B_*H_) { g_hf[i] = 0.f; g_hb[i] = 0.f; }
    }
}

// ---------------- bf16 hi/lo split: A3=[hi|hi|lo], B3=[hi|lo|hi] ----------------
__global__ void k_convW(const float* __restrict__ W)
{
    const size_t total = (size_t)V_*KO_;
    for (size_t i = (size_t)blockIdx.x*blockDim.x + threadIdx.x; i < total;
         i += (size_t)gridDim.x*blockDim.x) {
        size_t n = i / KO_, k = i % KO_;
        float w = W[i];
        __nv_bfloat16 h = __float2bfloat16(w);
        __nv_bfloat16 l = __float2bfloat16(w - __bfloat162float(h));
        __nv_bfloat16* row = g_B3 + n*K3_;
        row[k] = h; row[KO_+k] = l; row[2*KO_+k] = h;
    }
}
__global__ void k_convA()
{
    const size_t total = (size_t)MPAD_*KO_;
    for (size_t i = (size_t)blockIdx.x*blockDim.x + threadIdx.x; i < total;
         i += (size_t)gridDim.x*blockDim.x) {
        size_t m = i / KO_, k = i % KO_;
        float a = (m < (size_t)(ST_*B_)) ? g_feat[i] : 0.f;
        __nv_bfloat16 h = __float2bfloat16(a);
        __nv_bfloat16 l = __float2bfloat16(a - __bfloat162float(h));
        __nv_bfloat16* row = g_A3 + m*K3_;
        row[k] = h; row[KO_+k] = h; row[2*KO_+k] = l;
    }
}

// ---------------- HMMA output GEMM ----------------
#define LDS_ 40
__global__ __launch_bounds__(256, 2)
void k_outgemm(float* __restrict__ out, const float* __restrict__ bias)
{
    __shared__ __align__(16) __nv_bfloat16 sA[2][128*LDS_];
    __shared__ __align__(16) __nv_bfloat16 sB[2][128*LDS_];
    const int tid = threadIdx.x, wid = tid >> 5, lane = tid & 31;
    const int wm = wid >> 2, wn = wid & 3;
    const int m0 = blockIdx.x * 128;
    const int n0 = blockIdx.y * 128;

    float acc[4][4][4];
    #pragma unroll
    for (int i = 0; i < 4; i++)
        #pragma unroll
        for (int j = 0; j < 4; j++)
            #pragma unroll
            for (int q = 0; q < 4; q++) acc[i][j][q] = 0.f;

    const int NC = K3_ / 32;
    const int r0 = tid >> 2, sg0 = tid & 3;
    auto issue = [&](int c, int buf) {
        int kc = c * 32;
        #pragma unroll
        for (int h = 0; h < 2; h++) {
            int r = r0 + h*64;
            cpa16(s2u(&sA[buf][r*LDS_ + sg0*8]), g_A3 + (size_t)(m0 + r)*K3_ + kc + sg0*8);
            cpa16(s2u(&sB[buf][r*LDS_ + sg0*8]), g_B3 + (size_t)(n0 + r)*K3_ + kc + sg0*8);
        }
        asm volatile("cp.async.commit_group;");
    };

    issue(0, 0);
    for (int c = 0; c < NC; c++) {
        int buf = c & 1;
        if (c + 1 < NC) {
            issue(c + 1, buf ^ 1);
            asm volatile("cp.async.wait_group 1;" ::: "memory");
        } else {
            asm volatile("cp.async.wait_group 0;" ::: "memory");
        }
        __syncthreads();
        const u32 aB = s2u(&sA[buf][0]);
        const u32 bB = s2u(&sB[buf][0]);
        #pragma unroll
        for (int ks = 0; ks < 2; ks++) {
            u32 af[4][4], bf[4][2];
            #pragma unroll
            for (int fm = 0; fm < 4; fm++)
                ldmA4(aB + (u32)((wm*64 + fm*16 + (lane & 15))*(LDS_*2) + ks*32 + (lane >> 4)*16), af[fm]);
            #pragma unroll
            for (int fn = 0; fn < 4; fn++)
                ldmB2(bB + (u32)((wn*32 + fn*8 + (lane & 7))*(LDS_*2) + ks*32 + ((lane >> 3) & 1)*16), bf[fn]);
            #pragma unroll
            for (int fm = 0; fm < 4; fm++)
                #pragma unroll
                for (int fn = 0; fn < 4; fn++)
                    mma16816(acc[fm][fn], af[fm], bf[fn]);
        }
        __syncthreads();
    }

    #pragma unroll
    for (int fm = 0; fm < 4; fm++) {
        #pragma unroll
        for (int half = 0; half < 2; half++) {
            int m = m0 + wm*64 + fm*16 + (lane >> 2) + half*8;
            if (m >= ST_*B_) continue;
            float* orow = out + ((size_t)((m & 15)*ST_ + (m >> 4)))*V_;
            #pragma unroll
            for (int fn = 0; fn < 4; fn++) {
                int nc = n0 + wn*32 + fn*8 + (lane & 3)*2;
                float2 v;
                v.x = acc[fm][fn][half*2 + 0] + bias[nc];
                v.y = acc[fm][fn][half*2 + 1] + bias[nc + 1];
                *(float2*)(orow + nc) = v;
            }
        }
    }
}

// ---------------- SIMT f32 GEMM for the small matmuls ----------------
__global__ __launch_bounds__(256, 2)
void k_gemm(const float* __restrict__ A, const float* __restrict__ W,
            const float* __restrict__ bias, float* __restrict__ C,
            int M, int N, int K, int ldw)
{
    __shared__ float As[16][132];
    __shared__ float Bs[16][132];
    const int tid = threadIdx.x;
    const int tx = tid & 15, ty = tid >> 4;
    const int m0 = blockIdx.y * 128, n0 = blockIdx.x * 128;
    const int lr = tid >> 2, lc = (tid & 3) * 4;

    u64 acc[8][4];
    #pragma unroll
    for (int i = 0; i < 8; i++)
        #pragma unroll
        for (int j = 0; j < 4; j++) acc[i][j] = 0ULL;

    for (int k0 = 0; k0 < K; k0 += 16) {
        #pragma unroll
        for (int h = 0; h < 2; h++) {
            int m = m0 + lr + h*64;
            float4 v = (m < M) ? *(const float4*)(A + (size_t)m*K + k0 + lc)
                               : make_float4(0.f,0.f,0.f,0.f);
            As[lc+0][lr+h*64] = v.x; As[lc+1][lr+h*64] = v.y;
            As[lc+2][lr+h*64] = v.z; As[lc+3][lr+h*64] = v.w;
        }
        #pragma unroll
        for (int h = 0; h < 2; h++) {
            int n = n0 + lr + h*64;
            float4 v = *(const float4*)(W + (size_t)n*ldw + k0 + lc);
            Bs[lc+0][lr+h*64] = v.x; Bs[lc+1][lr+h*64] = v.y;
            Bs[lc+2][lr+h*64] = v.z; Bs[lc+3][lr+h*64] = v.w;
        }
        __syncthreads();
        #pragma unroll
        for (int k = 0; k < 16; k++) {
            float4 a0 = *(const float4*)&As[k][ty*8];
            float4 a1 = *(const float4*)&As[k][ty*8+4];
            float4 b0 = *(const float4*)&Bs[k][tx*8];
            float4 b1 = *(const float4*)&Bs[k][tx*8+4];
            float ra[8] = {a0.x,a0.y,a0.z,a0.w,a1.x,a1.y,a1.z,a1.w};
            u64 bp[4];
            bp[0] = f2pack(b0.x, b0.y); bp[1] = f2pack(b0.z, b0.w);
            bp[2] = f2pack(b1.x, b1.y); bp[3] = f2pack(b1.z, b1.w);
            #pragma unroll
            for (int i = 0; i < 8; i++) {
                u64 ap = f2pack(ra[i], ra[i]);
                f2fma(acc[i][0], ap, bp[0]); f2fma(acc[i][1], ap, bp[1]);
                f2fma(acc[i][2], ap, bp[2]); f2fma(acc[i][3], ap, bp[3]);
            }
        }
        __syncthreads();
    }
    #pragma unroll
    for (int i = 0; i < 8; i++) {
        int m = m0 + ty*8 + i;
        if (m >= M) continue;
        float* crow = C + (size_t)m*N;
        int nc = n0 + tx*8;
        #pragma unroll
        for (int j = 0; j < 4; j++) {
            float2 v = f2unpack(acc[i][j]);
            float c0 = v.x, c1 = v.y;
            if (bias) { c0 += bias[nc+2*j]; c1 += bias[nc+2*j+1]; }
            crow[nc+2*j] = c0; crow[nc+2*j+1] = c1;
        }
    }
}

// ---------------- persistent encoder: one launch, grid barrier per step ----------------
__global__ __launch_bounds__(256)
void k_enc(const float* __restrict__ Wf, const float* __restrict__ bf,
           const float* __restrict__ Wb, const float* __restrict__ bb,
           const int* __restrict__ len)
{
    __shared__ float hs[16*HP_];
    const int blk = blockIdx.x;
    const int dir = blk >> 5, jb = blk & 31;
    const int tid = threadIdx.x;
    const int b = tid & 15;
    const int j = jb*16 + (tid >> 4);
    const float* Whh = dir ? Wb : Wf;
    const float* bhh = dir ? bb : bf;
    float* hbase = dir ? g_hb : g_hf;
    const float* GIb = dir ? g_GI_b : g_GI_f;
    const int L = len[b];
    const float* Wr = Whh + (size_t)j*H_;
    const float* Wz = Wr + (size_t)H_*H_;
    const float* Wn = Wz + (size_t)H_*H_;
    const float br = bhh[j], bz = bhh[H_+j], bn = bhh[2*H_+j];

    for (int t = 0; t < S_; t++) {
        const float* hrow = hbase + (t & 1)*(B_*H_);
        for (int idx = tid; idx < B_*H_; idx += 256)
            hs[(idx >> 9)*HP_ + (idx & 511)] = hrow[idx];
        __syncthreads();

        float ar, az, an;
        dot3_512(hs + b*HP_, Wr, Wz, Wn, ar, az, an);
        const float* GI = GIb + ((size_t)(b*S_ + t))*H3_;
        float r = sigf(GI[j]       + ar + br);
        float z = sigf(GI[H_+j]    + az + bz);
        float n = tanhf(GI[2*H_+j] + r*(an + bn));
        float hold = hs[b*HP_ + j];
        float hnew = (1.f - z)*n + z*hold;
        bool valid = t < L;
        hbase[((t+1) & 1)*(B_*H_) + b*H_ + j] = valid ? hnew : hold;
        float o = valid ? hnew : 0.f;
        if (dir == 0) g_enc_out[((size_t)(b*S_+t))*H2_ + j] = o;
        else          g_out_bR [((size_t)(b*S_+t))*H_  + j] = o;
        gbar(64);
    }
}

__global__ void k_outbw(const int* __restrict__ len)
{
    int i = blockIdx.x*blockDim.x + threadIdx.x;
    if (i >= B_*S_*H_) return;
    int j = i % H_, s = (i / H_) % S_, b = i / (H_*S_);
    int L = len[b];
    int r = (s < L) ? (L-1-s) : s;
    g_enc_out[((size_t)(b*S_+s))*H2_ + H_ + j] = g_out_bR[((size_t)(b*S_+r))*H_ + j];
}

__global__ void k_bridge(const float* __restrict__ bridge_W, const float* __restrict__ bridge_b)
{
    const int tid = threadIdx.x;
    const int b = tid & 15, j = blockIdx.x * 16 + (tid >> 4);
    const float* Wrow = bridge_W + (size_t)j*H2_;
    const float* hf = g_hf + b*H_;
    const float* hb = g_hb + b*H_;
    float acc = 0.f;
    #pragma unroll 4
    for (int k = 0; k < H_; k += 4) {
        float4 h = *(const float4*)(hf + k);
        float4 w = *(const float4*)(Wrow + k);
        acc = fmaf(h.x,w.x, fmaf(h.y,w.y, fmaf(h.z,w.z, fmaf(h.w,w.w, acc))));
    }
    #pragma unroll 4
    for (int k = 0; k < H_; k += 4) {
        float4 h = *(const float4*)(hb + k);
        float4 w = *(const float4*)(Wrow + H_ + k);
        acc = fmaf(h.x,w.x, fmaf(h.y,w.y, fmaf(h.z,w.z, fmaf(h.w,w.w, acc))));
    }
    g_hdec[b*H_ + j] = tanhf(acc + bridge_b[j]);
}

// ---------------- persistent decoder: one launch, 4 grid barriers per step ----------------
__global__ __launch_bounds__(256)
void k_dec(const float* __restrict__ Wa_dec, const float* __restrict__ Wv,
           const int* __restrict__ src, const float* __restrict__ Whd,
           const float* __restrict__ bhd)
{
    __shared__ float hs[16*HP_];
    __shared__ float asmx[S_];
    const int blk = blockIdx.x, tid = threadIdx.x;
    const int lane = tid & 31, w = tid >> 5;
    const int b16 = tid & 15, ty = tid >> 4;

    for (int t = 0; t < ST_; t++) {
        // P1: stage h(t) in smem + dp (blocks 0..31)
        if (blk < 32) {
            const float* hrow = g_hdec + (t & 1)*(B_*H_);
            for (int idx = tid; idx < B_*H_; idx += 256)
                hs[(idx >> 9)*HP_ + (idx & 511)] = hrow[idx];
            __syncthreads();
            int j = blk*16 + ty;
            const float* wa = Wa_dec + (size_t)j*H_;
            const float* x = hs + b16*HP_;
            u64 a0 = 0, a1 = 0;
            #pragma unroll 8
            for (int k = 0; k < H_; k += 4) {
                float4 xv = *(const float4*)(x + k);
                float4 wv = *(const float4*)(wa + k);
                f2fma(a0, f2pack(xv.x, xv.y), f2pack(wv.x, wv.y));
                f2fma(a1, f2pack(xv.z, xv.w), f2pack(wv.z, wv.w));
            }
            float2 p = f2unpack(a0), q = f2unpack(a1);
            g_dps[b16*H_ + j] = (p.x + q.x) + (p.y + q.y);
        }
        gbar(64);

        // P2: masked energies, 4 (b,s) pairs per warp
        {
            int p0 = (blk*8 + w)*4;
            #pragma unroll
            for (int i = 0; i < 4; i++) {
                int pp = p0 + i, bb2 = pp >> 7, s = pp & 127;
                const float* er = g_encP + ((size_t)(bb2*S_ + s))*H_;
                const float* dp = g_dps + bb2*H_;
                float acc = 0.f;
                #pragma unroll
                for (int ii = 0; ii < 16; ii++) {
                    int k = lane + 32*ii;
                    acc = fmaf(tanhap(er[k] + dp[k]), Wv[k], acc);
                }
                #pragma unroll
                for (int o = 16; o; o >>= 1) acc += __shfl_xor_sync(0xffffffffu, acc, o);
                if (lane == 0)
                    g_esm[bb2*S_ + s] = (src[bb2*S_ + s] != 0) ? acc : -1e9f;
            }
        }
        gbar(64);

        // P3/P4: local softmax + ctx/gic slice (block = b*4 + q)
        {
            int b = blk >> 2, q = blk & 3;
            if (w == 0) {
                float v[4]; float m = -1e30f;
                #pragma unroll
                for (int i = 0; i < 4; i++) { v[i] = g_esm[b*S_ + lane + 32*i]; m = fmaxf(m, v[i]); }
                #pragma unroll
                for (int o = 16; o; o >>= 1) m = fmaxf(m, __shfl_xor_sync(0xffffffffu, m, o));
                float sum = 0.f;
                #pragma unroll
                for (int i = 0; i < 4; i++) { v[i] = expf(v[i] - m); sum += v[i]; }
                #pragma unroll
                for (int o = 16; o; o >>= 1) sum += __shfl_xor_sync(0xffffffffu, sum, o);
                float inv = 1.f / sum;
                #pragma unroll
                for (int i = 0; i < 4; i++) asmx[lane + 32*i] = v[i]*inv;
            }
            __syncthreads();
            size_t n = (size_t)t*B_ + b;
            #pragma unroll
            for (int cc = 0; cc < 3; cc++) {
                if (cc == 2 && tid >= 128) break;
                int c = q*640 + cc*256 + tid;
                const float* base; int stride; float* dst;
                if (c < H2_) {
                    base = g_enc_out + (size_t)b*S_*H2_ + c; stride = H2_;
                    dst = g_feat + n*KO_ + H_ + c;
                } else {
                    int c2 = c - H2_;
                    base = g_encW + (size_t)b*S_*H3_ + c2; stride = H3_;
                    dst = g_gict + b*H3_ + c2;
                }
                float acc = 0.f;
                #pragma unroll 4
                for (int s = 0; s < S_; s++)
                    acc = fmaf(asmx[s], base[(size_t)s*stride], acc);
                *dst = acc;
            }
        }
        gbar(64);

        // P5: GRU (blocks 0..31) — hs still holds h(t)
        if (blk < 32) {
            int j = blk*16 + ty;
            size_t n = (size_t)t*B_ + b16;
            float ar, az, an;
            dot3_512(hs + b16*HP_, Whd + (size_t)j*H_, Whd + (size_t)(H_+j)*H_,
                     Whd + (size_t)(2*H_+j)*H_, ar, az, an);
            const float* gie = g_GIe + n*H3_;
            const float* gic = g_gict + b16*H3_;
            float r  = sigf(gie[j]       + gic[j]       + ar + bhd[j]);
            float z  = sigf(gie[H_+j]    + gic[H_+j]    + az + bhd[H_+j]);
            float nn = tanhf(gie[2*H_+j] + gic[2*H_+j]  + r*(an + bhd[2*H_+j]));
            float hold = hs[b16*HP_ + j];
            float hnew = (1.f - z)*nn + z*hold;
            g_hdec[((t+1) & 1)*(B_*H_) + b16*H_ + j] = hnew;
            g_feat[n*KO_ + j] = hnew;
        }
        gbar(64);
    }
}

extern "C" void kernel_launch(void* const* d_in, const int* in_sizes, int n_in,
                              void* d_out, int out_size)
{
    const int*   src      = (const int*)d_in[0];
    const int*   len      = (const int*)d_in[1];
    const int*   tgt      = (const int*)d_in[2];
    const float* enc_emb  = (const float*)d_in[3];
    const float* W_ih_f   = (const float*)d_in[4];
    const float* W_hh_f   = (const float*)d_in[5];
    const float* b_ih_f   = (const float*)d_in[6];
    const float* b_hh_f   = (const float*)d_in[7];
    const float* W_ih_b   = (const float*)d_in[8];
    const float* W_hh_b   = (const float*)d_in[9];
    const float* b_ih_b   = (const float*)d_in[10];
    const float* b_hh_b   = (const float*)d_in[11];
    const float* bridge_W = (const float*)d_in[12];
    const float* bridge_b = (const float*)d_in[13];
    const float* dec_emb  = (const float*)d_in[14];
    const float* Wa_enc   = (const float*)d_in[15];
    const float* Wa_dec   = (const float*)d_in[16];
    const float* Wv       = (const float*)d_in[17];
    const float* W_ih_d   = (const float*)d_in[18];
    const float* W_hh_d   = (const float*)d_in[19];
    const float* b_ih_d   = (const float*)d_in[20];
    const float* b_hh_d   = (const float*)d_in[21];
    const float* out_W    = (const float*)d_in[22];
    const float* out_b    = (const float*)d_in[23];
    float* out = (float*)d_out;

    float *p_emb, *p_emb_rev, *p_emb_in, *p_GI_f, *p_GI_b, *p_GIe, *p_enc_out, *p_encP, *p_encW;
    cudaGetSymbolAddress((void**)&p_emb,     g_emb);
    cudaGetSymbolAddress((void**)&p_emb_rev, g_emb_rev);
    cudaGetSymbolAddress((void**)&p_emb_in,  g_emb_in);
    cudaGetSymbolAddress((void**)&p_GI_f,    g_GI_f);
    cudaGetSymbolAddress((void**)&p_GI_b,    g_GI_b);
    cudaGetSymbolAddress((void**)&p_GIe,     g_GIe);
    cudaGetSymbolAddress((void**)&p_enc_out, g_enc_out);
    cudaGetSymbolAddress((void**)&p_encP,    g_encP);
    cudaGetSymbolAddress((void**)&p_encW,    g_encW);

    k_convW<<<1024, 256>>>(out_W);
    k_gather<<<512, 256>>>(src, len, tgt, enc_emb, dec_emb);

    k_gemm<<<dim3(H3_/128, (B_*S_)/128), 256>>>(p_emb,     W_ih_f, b_ih_f, p_GI_f, B_*S_,  H3_, E_, E_);
    k_gemm<<<dim3(H3_/128, (B_*S_)/128), 256>>>(p_emb_rev, W_ih_b, b_ih_b, p_GI_b, B_*S_,  H3_, E_, E_);
    k_gemm<<<dim3(H3_/128, (ST_*B_+127)/128), 256>>>(p_emb_in, W_ih_d, b_ih_d, p_GIe, ST_*B_, H3_, E_, KD_);

    k_enc<<<64, 256>>>(W_hh_f, b_hh_f, W_hh_b, b_hh_b, len);

    k_outbw<<<(B_*S_*H_)/256, 256>>>(len);
    k_bridge<<<H_/16, 256>>>(bridge_W, bridge_b);
    k_gemm<<<dim3(H_/128, (B_*S_)/128), 256>>>(p_enc_out, Wa_enc, 0, p_encP, B_*S_, H_, H2_, H2_);
    k_gemm<<<dim3(H3_/128, (B_*S_)/128), 256>>>(p_enc_out, W_ih_d + E_, 0, p_encW, B_*S_, H3_, H2_, KD_);

    k_dec<<<64, 256>>>(Wa_dec, Wv, src, W_hh_d, b_hh_d);

    k_convA<<<1024, 256>>>();
    k_outgemm<<<dim3(MPAD_/128, V_/128), 256>>>(out, out_b);
}